// round 1
// baseline (speedup 1.0000x reference)
#include <cuda_runtime.h>
#include <math.h>

// Problem constants
#define BATCH 2
#define SEQ   2048
#define EMBD  2048
#define NH    16
#define NKVH  4
#define HD    128
#define MROWS (BATCH*SEQ)        // 4096
#define KVDIM (NKVH*HD)          // 512
#define QSCALE 0.08838834764831845f  // 1/sqrt(128)

// Scratch ( __device__ globals: allocation-free )
__device__ float g_q[MROWS * EMBD];    // [B,T,H,D]  = [4096,2048]
__device__ float g_k[MROWS * KVDIM];   // [B,T,KVH,D]= [4096,512]
__device__ float g_v[MROWS * KVDIM];
__device__ float g_att[MROWS * EMBD];  // attention out, [B,T,H,D]

// ---------------------------------------------------------------------------
// GEMM: C[m,n] = sum_k A[m,k]*W[n,k]   (A row-major MxK, W row-major NxK)
// BM=BN=64, BK=16, 256 threads, 4x4 microtile
// ---------------------------------------------------------------------------
#define BM 64
#define BN 64
#define BK 16

__global__ void __launch_bounds__(256)
gemm_qkv_kernel(const float* __restrict__ X,
                const float* __restrict__ Wq,
                const float* __restrict__ Wk,
                const float* __restrict__ Wv)
{
    __shared__ float As[BK][BM + 2];
    __shared__ float Bs[BK][BN + 2];

    const int n0 = blockIdx.x * BN;   // 0..3071
    const int m0 = blockIdx.y * BM;

    const float* W; int nb;
    if (n0 < 2048)      { W = Wq; nb = n0; }
    else if (n0 < 2560) { W = Wk; nb = n0 - 2048; }
    else                { W = Wv; nb = n0 - 2560; }

    const int tid = threadIdx.x;
    const int kk  = tid & 15;
    const int r0  = tid >> 4;     // 0..15
    const int tx  = tid & 15;
    const int ty  = tid >> 4;

    float acc[4][4] = {};

    for (int k0 = 0; k0 < EMBD; k0 += BK) {
        #pragma unroll
        for (int i = 0; i < 4; i++)
            As[kk][r0 + 16*i] = X[(size_t)(m0 + r0 + 16*i) * EMBD + k0 + kk];
        #pragma unroll
        for (int i = 0; i < 4; i++)
            Bs[kk][r0 + 16*i] = W[(size_t)(nb + r0 + 16*i) * EMBD + k0 + kk];
        __syncthreads();

        #pragma unroll
        for (int k = 0; k < BK; k++) {
            float a[4], b[4];
            #pragma unroll
            for (int i = 0; i < 4; i++) a[i] = As[k][ty*4 + i];
            #pragma unroll
            for (int j = 0; j < 4; j++) b[j] = Bs[k][tx*4 + j];
            #pragma unroll
            for (int i = 0; i < 4; i++)
                #pragma unroll
                for (int j = 0; j < 4; j++)
                    acc[i][j] += a[i] * b[j];
        }
        __syncthreads();
    }

    #pragma unroll
    for (int i = 0; i < 4; i++) {
        const int m = m0 + ty*4 + i;
        #pragma unroll
        for (int j = 0; j < 4; j++) {
            const int n = n0 + tx*4 + j;
            const float v = acc[i][j];
            if (n < 2048)      g_q[(size_t)m * EMBD  + n]          = v;
            else if (n < 2560) g_k[(size_t)m * KVDIM + (n - 2048)] = v;
            else               g_v[(size_t)m * KVDIM + (n - 2560)] = v;
        }
    }
}

__global__ void __launch_bounds__(256)
gemm_out_kernel(const float* __restrict__ Wo, float* __restrict__ out)
{
    __shared__ float As[BK][BM + 2];
    __shared__ float Bs[BK][BN + 2];

    const int n0 = blockIdx.x * BN;
    const int m0 = blockIdx.y * BM;

    const int tid = threadIdx.x;
    const int kk  = tid & 15;
    const int r0  = tid >> 4;
    const int tx  = tid & 15;
    const int ty  = tid >> 4;

    float acc[4][4] = {};

    for (int k0 = 0; k0 < EMBD; k0 += BK) {
        #pragma unroll
        for (int i = 0; i < 4; i++)
            As[kk][r0 + 16*i] = g_att[(size_t)(m0 + r0 + 16*i) * EMBD + k0 + kk];
        #pragma unroll
        for (int i = 0; i < 4; i++)
            Bs[kk][r0 + 16*i] = Wo[(size_t)(n0 + r0 + 16*i) * EMBD + k0 + kk];
        __syncthreads();

        #pragma unroll
        for (int k = 0; k < BK; k++) {
            float a[4], b[4];
            #pragma unroll
            for (int i = 0; i < 4; i++) a[i] = As[k][ty*4 + i];
            #pragma unroll
            for (int j = 0; j < 4; j++) b[j] = Bs[k][tx*4 + j];
            #pragma unroll
            for (int i = 0; i < 4; i++)
                #pragma unroll
                for (int j = 0; j < 4; j++)
                    acc[i][j] += a[i] * b[j];
        }
        __syncthreads();
    }

    #pragma unroll
    for (int i = 0; i < 4; i++) {
        const int m = m0 + ty*4 + i;
        #pragma unroll
        for (int j = 0; j < 4; j++)
            out[(size_t)m * EMBD + n0 + tx*4 + j] = acc[i][j];
    }
}

// ---------------------------------------------------------------------------
// RoPE (interleaved pairs, matches reference), in-place on g_q / g_k
// ---------------------------------------------------------------------------
#define NQPAIR (MROWS * NH   * (HD/2))   // 4,194,304
#define NKPAIR (MROWS * NKVH * (HD/2))   // 1,048,576

__global__ void rope_kernel()
{
    const int idx = blockIdx.x * blockDim.x + threadIdx.x;
    if (idx < NQPAIR) {
        const int row = idx >> 10;            // pairs per row = 16*64 = 1024
        const int rem = idx & 1023;
        const int i   = rem & 63;             // pair index within head
        const int off = row * EMBD + (rem >> 6) * HD + 2*i;
        const int t   = row & (SEQ - 1);
        const float theta = powf(10000.0f, -(float)i * (1.0f/64.0f));
        float s, c;
        sincosf((float)t * theta, &s, &c);
        const float xr = g_q[off], xi = g_q[off + 1];
        g_q[off]     = xr*c - xi*s;
        g_q[off + 1] = xr*s + xi*c;
    } else {
        const int j = idx - NQPAIR;
        if (j < NKPAIR) {
            const int row = j >> 8;           // pairs per row = 4*64 = 256
            const int rem = j & 255;
            const int i   = rem & 63;
            const int off = row * KVDIM + (rem >> 6) * HD + 2*i;
            const int t   = row & (SEQ - 1);
            const float theta = powf(10000.0f, -(float)i * (1.0f/64.0f));
            float s, c;
            sincosf((float)t * theta, &s, &c);
            const float xr = g_k[off], xi = g_k[off + 1];
            g_k[off]     = xr*c - xi*s;
            g_k[off + 1] = xr*s + xi*c;
        }
    }
}

// ---------------------------------------------------------------------------
// Flash attention, causal, GQA. One CTA per (b, h, 64-row q tile).
// smem: Qs[64][129], Ks[64][129], Vs[64][128], Ss[64][65], stats 3*64
// ---------------------------------------------------------------------------
#define QS_STR 129
#define SS_STR 65
#define FLASH_SMEM_FLOATS (64*QS_STR + 64*QS_STR + 64*128 + 64*SS_STR + 192)
#define FLASH_SMEM_BYTES  (FLASH_SMEM_FLOATS * 4)   // 116,224

__global__ void __launch_bounds__(256)
flash_kernel()
{
    extern __shared__ float sm[];
    float* Qs    = sm;
    float* Ks    = Qs + 64*QS_STR;
    float* Vs    = Ks + 64*QS_STR;
    float* Ss    = Vs + 64*128;
    float* sm_m  = Ss + 64*SS_STR;
    float* sm_l  = sm_m + 64;
    float* sm_al = sm_l + 64;

    const int tid = threadIdx.x;
    const int b   = blockIdx.z;
    const int h   = blockIdx.y;
    const int hk  = h >> 2;                 // GQA: groups = 4
    const int m0  = blockIdx.x * 64;
    const int tx  = tid & 15;
    const int ty  = tid >> 4;

    // Load Q tile (pre-scaled)
    for (int idx = tid; idx < 64*128; idx += 256) {
        const int r = idx >> 7, d = idx & 127;
        Qs[r*QS_STR + d] =
            g_q[(size_t)(b*SEQ + m0 + r) * EMBD + h*HD + d] * QSCALE;
    }
    if (tid < 64) { sm_m[tid] = -INFINITY; sm_l[tid] = 0.0f; }

    // O accumulator: thread owns row r=tid>>2, 32 cols starting at (tid&3)*32
    const int orow = tid >> 2;
    const int ocol = (tid & 3) * 32;
    float4 acc[8];
    #pragma unroll
    for (int q = 0; q < 8; q++) acc[q] = make_float4(0.f, 0.f, 0.f, 0.f);

    const int ntiles = blockIdx.x + 1;      // causal

    for (int jt = 0; jt < ntiles; jt++) {
        __syncthreads();
        // Load K tile (scalar, padded stride) and V tile (float4)
        for (int idx = tid; idx < 64*128; idx += 256) {
            const int r = idx >> 7, d = idx & 127;
            Ks[r*QS_STR + d] =
                g_k[(size_t)(b*SEQ + jt*64 + r) * KVDIM + hk*HD + d];
        }
        float4* Vs4 = (float4*)Vs;
        for (int idx = tid; idx < 64*32; idx += 256) {
            const int r = idx >> 5, d4 = idx & 31;
            Vs4[r*32 + d4] = ((const float4*)g_v)
                [((size_t)(b*SEQ + jt*64 + r) * KVDIM + hk*HD) / 4 + d4];
        }
        __syncthreads();

        // S = Q K^T  (4x4 per thread)
        {
            float s[4][4] = {};
            #pragma unroll 4
            for (int k = 0; k < 128; k++) {
                float a[4], bb[4];
                #pragma unroll
                for (int i = 0; i < 4; i++) a[i]  = Qs[(ty*4 + i)*QS_STR + k];
                #pragma unroll
                for (int j = 0; j < 4; j++) bb[j] = Ks[(tx*4 + j)*QS_STR + k];
                #pragma unroll
                for (int i = 0; i < 4; i++)
                    #pragma unroll
                    for (int j = 0; j < 4; j++)
                        s[i][j] += a[i] * bb[j];
            }
            #pragma unroll
            for (int i = 0; i < 4; i++) {
                const int qp = m0 + ty*4 + i;
                #pragma unroll
                for (int j = 0; j < 4; j++) {
                    const int kp = jt*64 + tx*4 + j;
                    Ss[(ty*4 + i)*SS_STR + tx*4 + j] =
                        (kp <= qp) ? s[i][j] : -INFINITY;
                }
            }
        }
        __syncthreads();

        // Online softmax (one thread per row)
        if (tid < 64) {
            const int r = tid;
            float tmax = -INFINITY;
            #pragma unroll 8
            for (int c = 0; c < 64; c++) tmax = fmaxf(tmax, Ss[r*SS_STR + c]);
            const float oldm = sm_m[r];
            const float newm = fmaxf(oldm, tmax);
            const float alph = expf(oldm - newm);
            float sum = 0.0f;
            #pragma unroll 8
            for (int c = 0; c < 64; c++) {
                const float p = expf(Ss[r*SS_STR + c] - newm);
                Ss[r*SS_STR + c] = p;
                sum += p;
            }
            sm_l[r]  = sm_l[r] * alph + sum;
            sm_m[r]  = newm;
            sm_al[r] = alph;
        }
        __syncthreads();

        // O = O*alpha + P @ V
        {
            const float al = sm_al[orow];
            #pragma unroll
            for (int q = 0; q < 8; q++) {
                acc[q].x *= al; acc[q].y *= al; acc[q].z *= al; acc[q].w *= al;
            }
            const float4* vbase = (const float4*)(Vs + ocol);
            #pragma unroll 2
            for (int kk = 0; kk < 64; kk++) {
                const float p = Ss[orow*SS_STR + kk];
                const float4* vr = vbase + kk * 32;
                #pragma unroll
                for (int q = 0; q < 8; q++) {
                    const float4 vv = vr[q];
                    acc[q].x += p * vv.x;
                    acc[q].y += p * vv.y;
                    acc[q].z += p * vv.z;
                    acc[q].w += p * vv.w;
                }
            }
        }
    }

    // Normalize and write [B,T,H,D]
    const float linv = 1.0f / sm_l[orow];
    float4* orow_ptr = (float4*)
        (g_att + (size_t)(b*SEQ + m0 + orow) * EMBD + h*HD + ocol);
    #pragma unroll
    for (int q = 0; q < 8; q++) {
        float4 o = acc[q];
        o.x *= linv; o.y *= linv; o.z *= linv; o.w *= linv;
        orow_ptr[q] = o;
    }
}

// ---------------------------------------------------------------------------
extern "C" void kernel_launch(void* const* d_in, const int* in_sizes, int n_in,
                              void* d_out, int out_size)
{
    const float* x  = (const float*)d_in[0];
    // d_in[1] = attention_mask: all-True in this problem; causal handled in-kernel
    const float* Wq = (const float*)d_in[2];
    const float* Wk = (const float*)d_in[3];
    const float* Wv = (const float*)d_in[4];
    const float* Wo = (const float*)d_in[5];
    float* out = (float*)d_out;

    cudaFuncSetAttribute(flash_kernel,
                         cudaFuncAttributeMaxDynamicSharedMemorySize,
                         FLASH_SMEM_BYTES);

    gemm_qkv_kernel<<<dim3(3072/BN, MROWS/BM), 256>>>(x, Wq, Wk, Wv);

    const int npairs = NQPAIR + NKPAIR;
    rope_kernel<<<(npairs + 255) / 256, 256>>>();

    flash_kernel<<<dim3(SEQ/64, NH, BATCH), 256, FLASH_SMEM_BYTES>>>();

    gemm_out_kernel<<<dim3(EMBD/BN, MROWS/BM), 256>>>(Wo, out);
}

// round 3
// speedup vs baseline: 7.0913x; 7.0913x over previous
#include <cuda_runtime.h>
#include <math.h>
#include <stdint.h>

// Problem constants
#define BATCH 2
#define SEQ   2048
#define EMBD  2048
#define NH    16
#define NKVH  4
#define HD    128
#define MROWS (BATCH*SEQ)        // 4096
#define KVDIM (NKVH*HD)          // 512
#define QSCALE 0.08838834764831845f  // 1/sqrt(128)

// Scratch (__device__ globals: allocation-free)
__device__ float g_q[MROWS * EMBD];    // [B,T,H,D]
__device__ float g_k[MROWS * KVDIM];   // [B,T,KVH,D]
__device__ float g_v[MROWS * KVDIM];
__device__ float g_att[MROWS * EMBD];  // attention out [B,T,H,D]

// ===========================================================================
// mma.sync tf32 helpers (compute_100-safe; no tcgen05)
// ===========================================================================
__device__ __forceinline__ uint32_t f2tf32(float f) {
    uint32_t u;
    asm("cvt.rna.tf32.f32 %0, %1;" : "=r"(u) : "f"(f));
    return u;
}

// D += A(16x8) * B(8x8);  A row-major frag (4 regs), B col-major frag (2 regs)
__device__ __forceinline__ void mma_tf32(float* d, const uint32_t* a, const uint32_t* b) {
    asm volatile(
        "mma.sync.aligned.m16n8k8.row.col.f32.tf32.tf32.f32 "
        "{%0,%1,%2,%3}, {%4,%5,%6,%7}, {%8,%9}, {%0,%1,%2,%3};"
        : "+f"(d[0]), "+f"(d[1]), "+f"(d[2]), "+f"(d[3])
        : "r"(a[0]), "r"(a[1]), "r"(a[2]), "r"(a[3]), "r"(b[0]), "r"(b[1]));
}

// ===========================================================================
// TF32 GEMM: C[m,n] = sum_k A[m,k] * B[n,k].  128x128 tile, BK=32, 8 warps.
// smem stride 36 floats: frag bank index (4r+c)&31 -> conflict-free.
// ===========================================================================
#define GBK 32
#define GSTR 36
#define GEMM_SM_U32 (128 * GSTR)           // per operand

struct GemmSm { uint32_t A[GEMM_SM_U32]; uint32_t B[GEMM_SM_U32]; };

__device__ __forceinline__ void gemm_mainloop(const float* __restrict__ Abase,
                                              const float* __restrict__ Bbase,
                                              GemmSm* sm, float acc[2][8][4])
{
    const int tid  = threadIdx.x;
    const int lane = tid & 31, g = lane >> 2, tig = lane & 3;
    const int w = tid >> 5, wm = w & 3, wn = w >> 2;

    int lrow[4], lc4[4];
    #pragma unroll
    for (int i = 0; i < 4; i++) { const int idx = tid + i*256; lrow[i] = idx >> 3; lc4[i] = idx & 7; }

    float4 pa[4], pb[4];
    #pragma unroll
    for (int i = 0; i < 4; i++) {
        pa[i] = *(const float4*)(Abase + (size_t)lrow[i] * EMBD + lc4[i]*4);
        pb[i] = *(const float4*)(Bbase + (size_t)lrow[i] * EMBD + lc4[i]*4);
    }

    for (int c = 0; c < EMBD / GBK; c++) {
        __syncthreads();
        #pragma unroll
        for (int i = 0; i < 4; i++) {
            const uint32_t off = lrow[i]*GSTR + lc4[i]*4;
            sm->A[off+0] = f2tf32(pa[i].x); sm->A[off+1] = f2tf32(pa[i].y);
            sm->A[off+2] = f2tf32(pa[i].z); sm->A[off+3] = f2tf32(pa[i].w);
            sm->B[off+0] = f2tf32(pb[i].x); sm->B[off+1] = f2tf32(pb[i].y);
            sm->B[off+2] = f2tf32(pb[i].z); sm->B[off+3] = f2tf32(pb[i].w);
        }
        __syncthreads();
        if (c < EMBD/GBK - 1) {
            const int k0 = (c+1) * GBK;
            #pragma unroll
            for (int i = 0; i < 4; i++) {
                pa[i] = *(const float4*)(Abase + (size_t)lrow[i]*EMBD + k0 + lc4[i]*4);
                pb[i] = *(const float4*)(Bbase + (size_t)lrow[i]*EMBD + k0 + lc4[i]*4);
            }
        }
        #pragma unroll
        for (int ks = 0; ks < 4; ks++) {
            const int kk = ks*8 + tig;
            uint32_t af[2][4];
            #pragma unroll
            for (int mf = 0; mf < 2; mf++) {
                const int r = (wm*32 + mf*16 + g) * GSTR + kk;
                af[mf][0] = sm->A[r];
                af[mf][1] = sm->A[r + 8*GSTR];
                af[mf][2] = sm->A[r + 4];
                af[mf][3] = sm->A[r + 8*GSTR + 4];
            }
            uint32_t bf[8][2];
            #pragma unroll
            for (int nf = 0; nf < 8; nf++) {
                const int r = (wn*64 + nf*8 + g) * GSTR + kk;
                bf[nf][0] = sm->B[r];
                bf[nf][1] = sm->B[r + 4];
            }
            #pragma unroll
            for (int mf = 0; mf < 2; mf++)
                #pragma unroll
                for (int nf = 0; nf < 8; nf++)
                    mma_tf32(acc[mf][nf], af[mf], bf[nf]);
        }
    }
}

__global__ void __launch_bounds__(256)
gemm_qkv_mma(const float* __restrict__ X,
             const float* __restrict__ Wq,
             const float* __restrict__ Wk,
             const float* __restrict__ Wv)
{
    __shared__ GemmSm sm;
    const int n0 = blockIdx.x * 128;
    const int m0 = blockIdx.y * 128;

    const float* W; int nb; float* dst; int ldd; int ncol;
    if (n0 < 2048)      { W = Wq; nb = n0;        dst = g_q; ldd = EMBD;  ncol = n0; }
    else if (n0 < 2560) { W = Wk; nb = n0 - 2048; dst = g_k; ldd = KVDIM; ncol = n0 - 2048; }
    else                { W = Wv; nb = n0 - 2560; dst = g_v; ldd = KVDIM; ncol = n0 - 2560; }

    float acc[2][8][4] = {};
    gemm_mainloop(X + (size_t)m0 * EMBD, W + (size_t)nb * EMBD, &sm, acc);

    const int tid = threadIdx.x, lane = tid & 31, g = lane >> 2, tig = lane & 3;
    const int w = tid >> 5, wm = w & 3, wn = w >> 2;
    #pragma unroll
    for (int mf = 0; mf < 2; mf++) {
        const int row = m0 + wm*32 + mf*16 + g;
        #pragma unroll
        for (int nf = 0; nf < 8; nf++) {
            const int col = ncol + wn*64 + nf*8 + 2*tig;
            *(float2*)(dst + (size_t)row * ldd + col) =
                make_float2(acc[mf][nf][0], acc[mf][nf][1]);
            *(float2*)(dst + (size_t)(row+8) * ldd + col) =
                make_float2(acc[mf][nf][2], acc[mf][nf][3]);
        }
    }
}

__global__ void __launch_bounds__(256)
gemm_out_mma(const float* __restrict__ Wo, float* __restrict__ out)
{
    __shared__ GemmSm sm;
    const int n0 = blockIdx.x * 128;
    const int m0 = blockIdx.y * 128;

    float acc[2][8][4] = {};
    gemm_mainloop(g_att + (size_t)m0 * EMBD, Wo + (size_t)n0 * EMBD, &sm, acc);

    const int tid = threadIdx.x, lane = tid & 31, g = lane >> 2, tig = lane & 3;
    const int w = tid >> 5, wm = w & 3, wn = w >> 2;
    #pragma unroll
    for (int mf = 0; mf < 2; mf++) {
        const int row = m0 + wm*32 + mf*16 + g;
        #pragma unroll
        for (int nf = 0; nf < 8; nf++) {
            const int col = n0 + wn*64 + nf*8 + 2*tig;
            *(float2*)(out + (size_t)row * EMBD + col) =
                make_float2(acc[mf][nf][0], acc[mf][nf][1]);
            *(float2*)(out + (size_t)(row+8) * EMBD + col) =
                make_float2(acc[mf][nf][2], acc[mf][nf][3]);
        }
    }
}

// ---------------------------------------------------------------------------
// RoPE (interleaved pairs), in-place on g_q / g_k
// ---------------------------------------------------------------------------
#define NQPAIR (MROWS * NH   * (HD/2))
#define NKPAIR (MROWS * NKVH * (HD/2))
#define LOG2_10000_D64 0.20761871046f    // log2(10000)/64

__global__ void rope_kernel()
{
    const int idx = blockIdx.x * blockDim.x + threadIdx.x;
    if (idx < NQPAIR) {
        const int row = idx >> 10;
        const int rem = idx & 1023;
        const int i   = rem & 63;
        const int off = row * EMBD + (rem >> 6) * HD + 2*i;
        const int t   = row & (SEQ - 1);
        const float theta = exp2f(-(float)i * LOG2_10000_D64);
        float s, c;
        sincosf((float)t * theta, &s, &c);
        const float xr = g_q[off], xi = g_q[off + 1];
        g_q[off]     = xr*c - xi*s;
        g_q[off + 1] = xr*s + xi*c;
    } else {
        const int j = idx - NQPAIR;
        if (j < NKPAIR) {
            const int row = j >> 8;
            const int rem = j & 255;
            const int i   = rem & 63;
            const int off = row * KVDIM + (rem >> 6) * HD + 2*i;
            const int t   = row & (SEQ - 1);
            const float theta = exp2f(-(float)i * LOG2_10000_D64);
            float s, c;
            sincosf((float)t * theta, &s, &c);
            const float xr = g_k[off], xi = g_k[off + 1];
            g_k[off]     = xr*c - xi*s;
            g_k[off + 1] = xr*s + xi*c;
        }
    }
}

// ---------------------------------------------------------------------------
// Flash attention via tf32 mma.sync. Tile 64 q-rows x 64 k-cols, 8 warps.
// warp -> (wm = w&3: 16-row m slice, wn = w>>2: 32-col S half / 64-col O half)
// Q fragments persist in registers (16 k-steps x 4 regs).
// smem strides: Ks 132 (4r+c pattern), Vs 136 (8k+n pattern), Ss 68.
// ---------------------------------------------------------------------------
#define KSTR 132
#define VSTR 136
#define SSTR 68
#define FLASH_SM_FLOATS (64*KSTR + 64*VSTR + 64*SSTR + 192)
#define FLASH_SMEM_BYTES (FLASH_SM_FLOATS * 4)   // 86784

__global__ void __launch_bounds__(256)
flash_mma()
{
    extern __shared__ float smf[];
    float* Ks    = smf;
    float* Vs    = Ks + 64*KSTR;
    float* Ss    = Vs + 64*VSTR;
    float* sm_m  = Ss + 64*SSTR;
    float* sm_l  = sm_m + 64;
    float* sm_al = sm_l + 64;
    uint32_t* KsU = (uint32_t*)Ks;
    uint32_t* VsU = (uint32_t*)Vs;
    uint32_t* SsU = (uint32_t*)Ss;

    const int tid = threadIdx.x, lane = tid & 31, g = lane >> 2, tig = lane & 3;
    const int w = tid >> 5, wm = w & 3, wn = w >> 2;
    const int b  = blockIdx.z;
    const int h  = blockIdx.y;
    const int hk = h >> 2;
    const int m0 = blockIdx.x * 64;

    // ---- stage Q into Ks buffer (scaled + tf32), then build Q fragments ----
    for (int idx = tid; idx < 64*32; idx += 256) {
        const int r = idx >> 5, d4 = idx & 31;
        const float4 v = *(const float4*)
            (g_q + (size_t)(b*SEQ + m0 + r) * EMBD + h*HD + d4*4);
        uint4 u;
        u.x = f2tf32(v.x * QSCALE); u.y = f2tf32(v.y * QSCALE);
        u.z = f2tf32(v.z * QSCALE); u.w = f2tf32(v.w * QSCALE);
        *(uint4*)&KsU[r*KSTR + d4*4] = u;
    }
    if (tid < 64) { sm_m[tid] = -INFINITY; sm_l[tid] = 0.0f; }
    __syncthreads();

    uint32_t qf[16][4];
    #pragma unroll
    for (int ks = 0; ks < 16; ks++) {
        const int r = (wm*16 + g) * KSTR + ks*8 + tig;
        qf[ks][0] = KsU[r];
        qf[ks][1] = KsU[r + 8*KSTR];
        qf[ks][2] = KsU[r + 4];
        qf[ks][3] = KsU[r + 8*KSTR + 4];
    }

    float of[8][4] = {};     // O fragments: 8 d-frags of 16x8

    const int ntiles = blockIdx.x + 1;
    for (int jt = 0; jt < ntiles; jt++) {
        __syncthreads();     // Q frags extracted / previous PV done
        // load K, V tiles (tf32)
        for (int idx = tid; idx < 64*32; idx += 256) {
            const int r = idx >> 5, d4 = idx & 31;
            const size_t gro = (size_t)(b*SEQ + jt*64 + r) * KVDIM + hk*HD + d4*4;
            const float4 kv = *(const float4*)(g_k + gro);
            uint4 uk;
            uk.x = f2tf32(kv.x); uk.y = f2tf32(kv.y);
            uk.z = f2tf32(kv.z); uk.w = f2tf32(kv.w);
            *(uint4*)&KsU[r*KSTR + d4*4] = uk;
            const float4 vv = *(const float4*)(g_v + gro);
            uint4 uv;
            uv.x = f2tf32(vv.x); uv.y = f2tf32(vv.y);
            uv.z = f2tf32(vv.z); uv.w = f2tf32(vv.w);
            *(uint4*)&VsU[r*VSTR + d4*4] = uv;
        }
        __syncthreads();

        // ---- S = Q K^T (warp covers 16 x 32) ----
        float sf[4][4] = {};
        #pragma unroll
        for (int ks = 0; ks < 16; ks++) {
            uint32_t bf[4][2];
            #pragma unroll
            for (int nf = 0; nf < 4; nf++) {
                const int r = (wn*32 + nf*8 + g) * KSTR + ks*8 + tig;
                bf[nf][0] = KsU[r];
                bf[nf][1] = KsU[r + 4];
            }
            #pragma unroll
            for (int nf = 0; nf < 4; nf++)
                mma_tf32(sf[nf], qf[ks], bf[nf]);
        }

        // ---- write S to Ss with causal mask ----
        {
            const int r0  = wm*16 + g;
            const int qp0 = m0 + r0;
            #pragma unroll
            for (int nf = 0; nf < 4; nf++) {
                const int col = wn*32 + nf*8 + 2*tig;
                const int kp  = jt*64 + col;
                *(float2*)&Ss[r0*SSTR + col] = make_float2(
                    (kp   <= qp0) ? sf[nf][0] : -INFINITY,
                    (kp+1 <= qp0) ? sf[nf][1] : -INFINITY);
                *(float2*)&Ss[(r0+8)*SSTR + col] = make_float2(
                    (kp   <= qp0+8) ? sf[nf][2] : -INFINITY,
                    (kp+1 <= qp0+8) ? sf[nf][3] : -INFINITY);
            }
        }
        __syncthreads();

        // ---- online softmax: 4 threads per row ----
        {
            const int row = tid >> 2, cb = (tid & 3) * 16;
            float tmax = -INFINITY;
            #pragma unroll
            for (int c = 0; c < 16; c++)
                tmax = fmaxf(tmax, Ss[row*SSTR + cb + c]);
            tmax = fmaxf(tmax, __shfl_xor_sync(0xffffffffu, tmax, 1));
            tmax = fmaxf(tmax, __shfl_xor_sync(0xffffffffu, tmax, 2));
            const float oldm = sm_m[row];
            const float newm = fmaxf(oldm, tmax);
            const float alph = __expf(oldm - newm);
            float sum = 0.0f;
            #pragma unroll
            for (int c = 0; c < 16; c++) {
                const float p = __expf(Ss[row*SSTR + cb + c] - newm);
                sum += p;
                SsU[row*SSTR + cb + c] = f2tf32(p);
            }
            sum += __shfl_xor_sync(0xffffffffu, sum, 1);
            sum += __shfl_xor_sync(0xffffffffu, sum, 2);
            if ((tid & 3) == 0) {
                sm_l[row]  = sm_l[row] * alph + sum;
                sm_m[row]  = newm;
                sm_al[row] = alph;
            }
        }
        __syncthreads();

        // ---- rescale O fragments ----
        {
            const float al0 = sm_al[wm*16 + g];
            const float al1 = sm_al[wm*16 + g + 8];
            #pragma unroll
            for (int nf = 0; nf < 8; nf++) {
                of[nf][0] *= al0; of[nf][1] *= al0;
                of[nf][2] *= al1; of[nf][3] *= al1;
            }
        }

        // ---- O += P V  (warp covers 16 x 64 of O) ----
        #pragma unroll
        for (int ks = 0; ks < 8; ks++) {
            uint32_t af[4];
            {
                const int r = (wm*16 + g) * SSTR + ks*8 + tig;
                af[0] = SsU[r];
                af[1] = SsU[r + 8*SSTR];
                af[2] = SsU[r + 4];
                af[3] = SsU[r + 8*SSTR + 4];
            }
            uint32_t bf[8][2];
            #pragma unroll
            for (int nf = 0; nf < 8; nf++) {
                const int dcol = wn*64 + nf*8 + g;
                bf[nf][0] = VsU[(ks*8 + tig)     * VSTR + dcol];
                bf[nf][1] = VsU[(ks*8 + tig + 4) * VSTR + dcol];
            }
            #pragma unroll
            for (int nf = 0; nf < 8; nf++)
                mma_tf32(of[nf], af, bf[nf]);
        }
    }

    // ---- normalize & write O ----
    {
        const float l0 = 1.0f / sm_l[wm*16 + g];
        const float l1 = 1.0f / sm_l[wm*16 + g + 8];
        const int row = m0 + wm*16 + g;
        #pragma unroll
        for (int nf = 0; nf < 8; nf++) {
            const int dcol = wn*64 + nf*8 + 2*tig;
            *(float2*)(g_att + (size_t)(b*SEQ + row) * EMBD + h*HD + dcol) =
                make_float2(of[nf][0]*l0, of[nf][1]*l0);
            *(float2*)(g_att + (size_t)(b*SEQ + row + 8) * EMBD + h*HD + dcol) =
                make_float2(of[nf][2]*l1, of[nf][3]*l1);
        }
    }
}

// ---------------------------------------------------------------------------
extern "C" void kernel_launch(void* const* d_in, const int* in_sizes, int n_in,
                              void* d_out, int out_size)
{
    const float* x  = (const float*)d_in[0];
    // d_in[1] = attention_mask (all True); causal handled in-kernel
    const float* Wq = (const float*)d_in[2];
    const float* Wk = (const float*)d_in[3];
    const float* Wv = (const float*)d_in[4];
    const float* Wo = (const float*)d_in[5];
    float* out = (float*)d_out;

    cudaFuncSetAttribute(flash_mma,
                         cudaFuncAttributeMaxDynamicSharedMemorySize, FLASH_SMEM_BYTES);

    gemm_qkv_mma<<<dim3(3072/128, MROWS/128), 256>>>(x, Wq, Wk, Wv);

    const int npairs = NQPAIR + NKPAIR;
    rope_kernel<<<(npairs + 255) / 256, 256>>>();

    flash_mma<<<dim3(SEQ/64, NH, BATCH), 256, FLASH_SMEM_BYTES>>>();

    gemm_out_mma<<<dim3(EMBD/128, MROWS/128), 256>>>(Wo, out);
}

// round 5
// speedup vs baseline: 7.2472x; 1.0220x over previous
#include <cuda_runtime.h>
#include <math.h>
#include <stdint.h>

// Problem constants
#define BATCH 2
#define SEQ   2048
#define EMBD  2048
#define NH    16
#define NKVH  4
#define HD    128
#define MROWS (BATCH*SEQ)        // 4096
#define KVDIM (NKVH*HD)          // 512
#define QSCALE 0.08838834764831845f  // 1/sqrt(128)

// Scratch (__device__ globals: allocation-free)
__device__ float g_q[MROWS * EMBD];    // [B,T,H,D]
__device__ float g_k[MROWS * KVDIM];   // [B,T,KVH,D]
__device__ float g_v[MROWS * KVDIM];
__device__ float g_att[MROWS * EMBD];  // attention out [B,T,H,D]
__device__ float2 g_rt[SEQ * 64];      // rope table: (cos, sin) per (t, i)

// ===========================================================================
// mma.sync tf32 + cp.async helpers (compute_100-safe)
// ===========================================================================
__device__ __forceinline__ uint32_t f2tf32(float f) {
    uint32_t u;
    asm("cvt.rna.tf32.f32 %0, %1;" : "=r"(u) : "f"(f));
    return u;
}

__device__ __forceinline__ void mma_tf32(float* d, const uint32_t* a, const uint32_t* b) {
    asm volatile(
        "mma.sync.aligned.m16n8k8.row.col.f32.tf32.tf32.f32 "
        "{%0,%1,%2,%3}, {%4,%5,%6,%7}, {%8,%9}, {%0,%1,%2,%3};"
        : "+f"(d[0]), "+f"(d[1]), "+f"(d[2]), "+f"(d[3])
        : "r"(a[0]), "r"(a[1]), "r"(a[2]), "r"(a[3]), "r"(b[0]), "r"(b[1]));
}

__device__ __forceinline__ uint32_t smem_addr_u32(const void* p) {
    uint32_t a;
    asm("{ .reg .u64 t; cvta.to.shared.u64 t, %1; cvt.u32.u64 %0, t; }"
        : "=r"(a) : "l"(p));
    return a;
}
__device__ __forceinline__ void cp_async16(uint32_t smem, const void* g) {
    asm volatile("cp.async.cg.shared.global [%0], [%1], 16;" :: "r"(smem), "l"(g));
}
#define CP_ASYNC_COMMIT() asm volatile("cp.async.commit_group;" ::: "memory")
#define CP_ASYNC_WAIT(n)  asm volatile("cp.async.wait_group %0;" :: "n"(n) : "memory")

// ===========================================================================
// TF32 GEMM: C[m,n] = sum_k A[m,k] * B[n,k].  128x128 tile, BK=32, 8 warps.
// smem stride 36: frag bank index (4r+c)&31 conflict-free.
// ===========================================================================
#define GBK 32
#define GSTR 36
#define GEMM_SM_U32 (128 * GSTR)

struct GemmSm { uint32_t A[GEMM_SM_U32]; uint32_t B[GEMM_SM_U32]; };

__device__ __forceinline__ void gemm_mainloop(const float* __restrict__ Abase,
                                              const float* __restrict__ Bbase,
                                              GemmSm* sm, float acc[2][8][4])
{
    const int tid  = threadIdx.x;
    const int lane = tid & 31, g = lane >> 2, tig = lane & 3;
    const int w = tid >> 5, wm = w & 3, wn = w >> 2;

    int lrow[4], lc4[4];
    #pragma unroll
    for (int i = 0; i < 4; i++) { const int idx = tid + i*256; lrow[i] = idx >> 3; lc4[i] = idx & 7; }

    float4 pa[4], pb[4];
    #pragma unroll
    for (int i = 0; i < 4; i++) {
        pa[i] = *(const float4*)(Abase + (size_t)lrow[i] * EMBD + lc4[i]*4);
        pb[i] = *(const float4*)(Bbase + (size_t)lrow[i] * EMBD + lc4[i]*4);
    }

    for (int c = 0; c < EMBD / GBK; c++) {
        __syncthreads();
        #pragma unroll
        for (int i = 0; i < 4; i++) {
            const uint32_t off = lrow[i]*GSTR + lc4[i]*4;
            sm->A[off+0] = f2tf32(pa[i].x); sm->A[off+1] = f2tf32(pa[i].y);
            sm->A[off+2] = f2tf32(pa[i].z); sm->A[off+3] = f2tf32(pa[i].w);
            sm->B[off+0] = f2tf32(pb[i].x); sm->B[off+1] = f2tf32(pb[i].y);
            sm->B[off+2] = f2tf32(pb[i].z); sm->B[off+3] = f2tf32(pb[i].w);
        }
        __syncthreads();
        if (c < EMBD/GBK - 1) {
            const int k0 = (c+1) * GBK;
            #pragma unroll
            for (int i = 0; i < 4; i++) {
                pa[i] = *(const float4*)(Abase + (size_t)lrow[i]*EMBD + k0 + lc4[i]*4);
                pb[i] = *(const float4*)(Bbase + (size_t)lrow[i]*EMBD + k0 + lc4[i]*4);
            }
        }
        #pragma unroll
        for (int ks = 0; ks < 4; ks++) {
            const int kk = ks*8 + tig;
            uint32_t af[2][4];
            #pragma unroll
            for (int mf = 0; mf < 2; mf++) {
                const int r = (wm*32 + mf*16 + g) * GSTR + kk;
                af[mf][0] = sm->A[r];
                af[mf][1] = sm->A[r + 8*GSTR];
                af[mf][2] = sm->A[r + 4];
                af[mf][3] = sm->A[r + 8*GSTR + 4];
            }
            uint32_t bf[8][2];
            #pragma unroll
            for (int nf = 0; nf < 8; nf++) {
                const int r = (wn*64 + nf*8 + g) * GSTR + kk;
                bf[nf][0] = sm->B[r];
                bf[nf][1] = sm->B[r + 4];
            }
            #pragma unroll
            for (int mf = 0; mf < 2; mf++)
                #pragma unroll
                for (int nf = 0; nf < 8; nf++)
                    mma_tf32(acc[mf][nf], af[mf], bf[nf]);
        }
    }
}

__global__ void __launch_bounds__(256)
gemm_qkv_mma(const float* __restrict__ X,
             const float* __restrict__ Wq,
             const float* __restrict__ Wk,
             const float* __restrict__ Wv)
{
    __shared__ GemmSm sm;
    const int n0 = blockIdx.x * 128;
    const int m0 = blockIdx.y * 128;

    const float* W; int nb; float* dst; int ldd; int ncol;
    if (n0 < 2048)      { W = Wq; nb = n0;        dst = g_q; ldd = EMBD;  ncol = n0; }
    else if (n0 < 2560) { W = Wk; nb = n0 - 2048; dst = g_k; ldd = KVDIM; ncol = n0 - 2048; }
    else                { W = Wv; nb = n0 - 2560; dst = g_v; ldd = KVDIM; ncol = n0 - 2560; }

    float acc[2][8][4] = {};
    gemm_mainloop(X + (size_t)m0 * EMBD, W + (size_t)nb * EMBD, &sm, acc);

    const int tid = threadIdx.x, lane = tid & 31, g = lane >> 2, tig = lane & 3;
    const int w = tid >> 5, wm = w & 3, wn = w >> 2;
    #pragma unroll
    for (int mf = 0; mf < 2; mf++) {
        const int row = m0 + wm*32 + mf*16 + g;
        #pragma unroll
        for (int nf = 0; nf < 8; nf++) {
            const int col = ncol + wn*64 + nf*8 + 2*tig;
            *(float2*)(dst + (size_t)row * ldd + col) =
                make_float2(acc[mf][nf][0], acc[mf][nf][1]);
            *(float2*)(dst + (size_t)(row+8) * ldd + col) =
                make_float2(acc[mf][nf][2], acc[mf][nf][3]);
        }
    }
}

__global__ void __launch_bounds__(256)
gemm_out_mma(const float* __restrict__ Wo, float* __restrict__ out)
{
    __shared__ GemmSm sm;
    const int n0 = blockIdx.x * 128;
    const int m0 = blockIdx.y * 128;

    float acc[2][8][4] = {};
    gemm_mainloop(g_att + (size_t)m0 * EMBD, Wo + (size_t)n0 * EMBD, &sm, acc);

    const int tid = threadIdx.x, lane = tid & 31, g = lane >> 2, tig = lane & 3;
    const int w = tid >> 5, wm = w & 3, wn = w >> 2;
    #pragma unroll
    for (int mf = 0; mf < 2; mf++) {
        const int row = m0 + wm*32 + mf*16 + g;
        #pragma unroll
        for (int nf = 0; nf < 8; nf++) {
            const int col = n0 + wn*64 + nf*8 + 2*tig;
            *(float2*)(out + (size_t)row * EMBD + col) =
                make_float2(acc[mf][nf][0], acc[mf][nf][1]);
            *(float2*)(out + (size_t)(row+8) * EMBD + col) =
                make_float2(acc[mf][nf][2], acc[mf][nf][3]);
        }
    }
}

// ---------------------------------------------------------------------------
// RoPE: precomputed cos/sin table, then a pure-bandwidth rotate pass
// ---------------------------------------------------------------------------
#define NQPAIR (MROWS * NH   * (HD/2))
#define NKPAIR (MROWS * NKVH * (HD/2))
#define LOG2_10000_D64 0.20761871046f    // log2(10000)/64

__global__ void rope_table_kernel()
{
    const int idx = blockIdx.x * blockDim.x + threadIdx.x;  // SEQ*64
    if (idx >= SEQ * 64) return;
    const int t = idx >> 6, i = idx & 63;
    const float theta = exp2f(-(float)i * LOG2_10000_D64);
    float s, c;
    sincosf((float)t * theta, &s, &c);
    g_rt[idx] = make_float2(c, s);
}

__global__ void rope_kernel()
{
    const int idx = blockIdx.x * blockDim.x + threadIdx.x;
    if (idx < NQPAIR) {
        const int row = idx >> 10;
        const int rem = idx & 1023;
        const int i   = rem & 63;
        const int t   = row & (SEQ - 1);
        const float2 cs = g_rt[t*64 + i];
        float2* p = (float2*)(g_q + (size_t)row * EMBD + (rem >> 6) * HD + 2*i);
        const float2 v = *p;
        *p = make_float2(v.x*cs.x - v.y*cs.y, v.x*cs.y + v.y*cs.x);
    } else {
        const int j = idx - NQPAIR;
        if (j < NKPAIR) {
            const int row = j >> 8;
            const int rem = j & 255;
            const int i   = rem & 63;
            const int t   = row & (SEQ - 1);
            const float2 cs = g_rt[t*64 + i];
            float2* p = (float2*)(g_k + (size_t)row * KVDIM + (rem >> 6) * HD + 2*i);
            const float2 v = *p;
            *p = make_float2(v.x*cs.x - v.y*cs.y, v.x*cs.y + v.y*cs.x);
        }
    }
}

// ---------------------------------------------------------------------------
// Flash attention, tf32 mma.sync, cp.async double-buffered K/V.
// Tile 64 q-rows x 64 k-cols, 8 warps (wm = w&3 m-slice, wn = w>>2 col half).
// K/V stored as raw fp32 (mma truncates to tf32 in HW).
// ---------------------------------------------------------------------------
#define KSTR 132
#define VSTR 136
#define SSTR 68
#define KBUF (64*KSTR)
#define VBUF (64*VSTR)
#define FLASH_SM_FLOATS (2*KBUF + 2*VBUF + 64*SSTR + 192)
#define FLASH_SMEM_BYTES (FLASH_SM_FLOATS * 4)   // 155,392

__device__ __forceinline__ void flash_load_tile(uint32_t smb, int bi,
                                                const float* kg, const float* vg,
                                                int tid)
{
    const uint32_t kbase = smb + (uint32_t)(bi * KBUF) * 4u;
    const uint32_t vbase = smb + (uint32_t)(2*KBUF + bi * VBUF) * 4u;
    #pragma unroll
    for (int i = 0; i < 8; i++) {
        const int idx = tid + i*256;
        const int r = idx >> 5, d4 = idx & 31;
        cp_async16(kbase + (uint32_t)(r*KSTR + d4*4)*4u, kg + (size_t)r*KVDIM + d4*4);
        cp_async16(vbase + (uint32_t)(r*VSTR + d4*4)*4u, vg + (size_t)r*KVDIM + d4*4);
    }
    CP_ASYNC_COMMIT();
}

__global__ void __launch_bounds__(256)
flash_mma()
{
    extern __shared__ float smf[];
    const uint32_t smb = smem_addr_u32(smf);
    float* Ss    = smf + 2*KBUF + 2*VBUF;
    float* sm_m  = Ss + 64*SSTR;
    float* sm_l  = sm_m + 64;
    float* sm_al = sm_l + 64;
    uint32_t* SsU = (uint32_t*)Ss;

    const int tid = threadIdx.x, lane = tid & 31, g = lane >> 2, tig = lane & 3;
    const int w = tid >> 5, wm = w & 3, wn = w >> 2;
    const int b  = blockIdx.z;
    const int h  = blockIdx.y;
    const int hk = h >> 2;
    const int qt = (int)gridDim.x - 1 - (int)blockIdx.x;   // heavy-first
    const int m0 = qt * 64;
    const int nt = qt + 1;

    const float* kg0 = g_k + (size_t)(b*SEQ) * KVDIM + hk*HD;
    const float* vg0 = g_v + (size_t)(b*SEQ) * KVDIM + hk*HD;

    // ---- stage Q (scaled, tf32) into K buffer 0, build Q fragments ----
    {
        uint32_t* K0U = (uint32_t*)smf;
        for (int idx = tid; idx < 64*32; idx += 256) {
            const int r = idx >> 5, d4 = idx & 31;
            const float4 v = *(const float4*)
                (g_q + (size_t)(b*SEQ + m0 + r) * EMBD + h*HD + d4*4);
            uint4 u;
            u.x = f2tf32(v.x * QSCALE); u.y = f2tf32(v.y * QSCALE);
            u.z = f2tf32(v.z * QSCALE); u.w = f2tf32(v.w * QSCALE);
            *(uint4*)&K0U[r*KSTR + d4*4] = u;
        }
        if (tid < 64) { sm_m[tid] = -INFINITY; sm_l[tid] = 0.0f; }
        __syncthreads();
    }

    uint32_t qf[16][4];
    {
        const uint32_t* K0U = (const uint32_t*)smf;
        #pragma unroll
        for (int ks = 0; ks < 16; ks++) {
            const int r = (wm*16 + g) * KSTR + ks*8 + tig;
            qf[ks][0] = K0U[r];
            qf[ks][1] = K0U[r + 8*KSTR];
            qf[ks][2] = K0U[r + 4];
            qf[ks][3] = K0U[r + 8*KSTR + 4];
        }
    }
    __syncthreads();     // all Q frags extracted before cp.async overwrites buf0

    // ---- prologue prefetch: tiles 0 and 1 ----
    flash_load_tile(smb, 0, kg0, vg0, tid);
    if (nt > 1) flash_load_tile(smb, 1, kg0 + (size_t)64*KVDIM, vg0 + (size_t)64*KVDIM, tid);

    float of[8][4] = {};

    for (int jt = 0; jt < nt; jt++) {
        if (jt + 1 < nt) { CP_ASYNC_WAIT(1); } else { CP_ASYNC_WAIT(0); }
        __syncthreads();

        const uint32_t* KtU = (const uint32_t*)(smf + (jt & 1) * KBUF);
        const uint32_t* VtU = (const uint32_t*)(smf + 2*KBUF + (jt & 1) * VBUF);

        // ---- S = Q K^T (warp covers 16 x 32) ----
        float sf[4][4] = {};
        #pragma unroll
        for (int ks = 0; ks < 16; ks++) {
            uint32_t bfr[4][2];
            #pragma unroll
            for (int nf = 0; nf < 4; nf++) {
                const int r = (wn*32 + nf*8 + g) * KSTR + ks*8 + tig;
                bfr[nf][0] = KtU[r];
                bfr[nf][1] = KtU[r + 4];
            }
            #pragma unroll
            for (int nf = 0; nf < 4; nf++)
                mma_tf32(sf[nf], qf[ks], bfr[nf]);
        }

        // ---- write S with causal mask ----
        {
            const int r0  = wm*16 + g;
            const int qp0 = m0 + r0;
            #pragma unroll
            for (int nf = 0; nf < 4; nf++) {
                const int col = wn*32 + nf*8 + 2*tig;
                const int kp  = jt*64 + col;
                *(float2*)&Ss[r0*SSTR + col] = make_float2(
                    (kp   <= qp0) ? sf[nf][0] : -INFINITY,
                    (kp+1 <= qp0) ? sf[nf][1] : -INFINITY);
                *(float2*)&Ss[(r0+8)*SSTR + col] = make_float2(
                    (kp   <= qp0+8) ? sf[nf][2] : -INFINITY,
                    (kp+1 <= qp0+8) ? sf[nf][3] : -INFINITY);
            }
        }
        __syncthreads();

        // ---- online softmax (4 threads / row) ----
        {
            const int row = tid >> 2, cb = (tid & 3) * 16;
            float tmax = -INFINITY;
            #pragma unroll
            for (int c = 0; c < 16; c++)
                tmax = fmaxf(tmax, Ss[row*SSTR + cb + c]);
            tmax = fmaxf(tmax, __shfl_xor_sync(0xffffffffu, tmax, 1));
            tmax = fmaxf(tmax, __shfl_xor_sync(0xffffffffu, tmax, 2));
            const float oldm = sm_m[row];
            const float newm = fmaxf(oldm, tmax);
            const float alph = __expf(oldm - newm);
            float sum = 0.0f;
            #pragma unroll
            for (int c = 0; c < 16; c++) {
                const float p = __expf(Ss[row*SSTR + cb + c] - newm);
                sum += p;
                SsU[row*SSTR + cb + c] = f2tf32(p);
            }
            sum += __shfl_xor_sync(0xffffffffu, sum, 1);
            sum += __shfl_xor_sync(0xffffffffu, sum, 2);
            if ((tid & 3) == 0) {
                sm_l[row]  = sm_l[row] * alph + sum;
                sm_m[row]  = newm;
                sm_al[row] = alph;
            }
        }
        __syncthreads();

        // ---- rescale O, then O += P V ----
        {
            const float al0 = sm_al[wm*16 + g];
            const float al1 = sm_al[wm*16 + g + 8];
            #pragma unroll
            for (int nf = 0; nf < 8; nf++) {
                of[nf][0] *= al0; of[nf][1] *= al0;
                of[nf][2] *= al1; of[nf][3] *= al1;
            }
        }
        #pragma unroll
        for (int ks = 0; ks < 8; ks++) {
            uint32_t af[4];
            {
                const int r = (wm*16 + g) * SSTR + ks*8 + tig;
                af[0] = SsU[r];
                af[1] = SsU[r + 8*SSTR];
                af[2] = SsU[r + 4];
                af[3] = SsU[r + 8*SSTR + 4];
            }
            uint32_t bfr[8][2];
            #pragma unroll
            for (int nf = 0; nf < 8; nf++) {
                const int dcol = wn*64 + nf*8 + g;
                bfr[nf][0] = VtU[(ks*8 + tig)     * VSTR + dcol];
                bfr[nf][1] = VtU[(ks*8 + tig + 4) * VSTR + dcol];
            }
            #pragma unroll
            for (int nf = 0; nf < 8; nf++)
                mma_tf32(of[nf], af, bfr[nf]);
        }
        __syncthreads();    // all reads of this buffer done

        if (jt + 2 < nt)
            flash_load_tile(smb, jt & 1,
                            kg0 + (size_t)(jt+2)*64*KVDIM,
                            vg0 + (size_t)(jt+2)*64*KVDIM, tid);
    }

    // ---- normalize & write O ----
    {
        const float l0 = 1.0f / sm_l[wm*16 + g];
        const float l1 = 1.0f / sm_l[wm*16 + g + 8];
        const int row = m0 + wm*16 + g;
        #pragma unroll
        for (int nf = 0; nf < 8; nf++) {
            const int dcol = wn*64 + nf*8 + 2*tig;
            *(float2*)(g_att + (size_t)(b*SEQ + row) * EMBD + h*HD + dcol) =
                make_float2(of[nf][0]*l0, of[nf][1]*l0);
            *(float2*)(g_att + (size_t)(b*SEQ + row + 8) * EMBD + h*HD + dcol) =
                make_float2(of[nf][2]*l1, of[nf][3]*l1);
        }
    }
}

// ---------------------------------------------------------------------------
extern "C" void kernel_launch(void* const* d_in, const int* in_sizes, int n_in,
                              void* d_out, int out_size)
{
    const float* x  = (const float*)d_in[0];
    // d_in[1] = attention_mask (all True); causal handled in-kernel
    const float* Wq = (const float*)d_in[2];
    const float* Wk = (const float*)d_in[3];
    const float* Wv = (const float*)d_in[4];
    const float* Wo = (const float*)d_in[5];
    float* out = (float*)d_out;

    cudaFuncSetAttribute(flash_mma,
                         cudaFuncAttributeMaxDynamicSharedMemorySize, FLASH_SMEM_BYTES);

    rope_table_kernel<<<(SEQ*64 + 255)/256, 256>>>();

    gemm_qkv_mma<<<dim3(3072/128, MROWS/128), 256>>>(x, Wq, Wk, Wv);

    const int npairs = NQPAIR + NKPAIR;
    rope_kernel<<<(npairs + 255) / 256, 256>>>();

    flash_mma<<<dim3(SEQ/64, NH, BATCH), 256, FLASH_SMEM_BYTES>>>();

    gemm_out_mma<<<dim3(EMBD/128, MROWS/128), 256>>>(Wo, out);
}